// round 5
// baseline (speedup 1.0000x reference)
#include <cuda_runtime.h>
#include <cstdint>

#define BB   128
#define TT   256
#define INSZ 512
#define HH   1024
#define G4   4096
#define ONN  512

// ---------------- device scratch (no allocation allowed) ----------------
__device__ float d_Wx[G4 * INSZ];                      // [4096,512]
__device__ float d_Wh[(size_t)G4 * HH];                // [4096,1024]
__device__ float d_bias[G4];
__device__ float d_GX[(size_t)BB * TT * G4];           // [t*128+b][4096]
__device__ float d_HS[(size_t)(TT + 1) * BB * HH];     // slot t = h_{t-1}
__device__ float d_C[BB * HH];                         // cell state

// ---------------- helpers ----------------
__device__ __forceinline__ float tf32r(float x) {
    uint32_t r; asm("cvt.rna.tf32.f32 %0, %1;" : "=r"(r) : "f"(x));
    return __uint_as_float(r);
}
__device__ __forceinline__ float sigf(float x) { return 1.f / (1.f + __expf(-x)); }
__device__ __forceinline__ float tanhf_(float x) {
    float e = __expf(-2.f * fabsf(x));
    float r = (1.f - e) / (1.f + e);
    return copysignf(r, x);
}
__device__ __forceinline__ void mma8(float* c, const uint32_t* a, const uint32_t* b) {
    asm volatile(
        "mma.sync.aligned.m16n8k8.row.col.f32.tf32.tf32.f32 "
        "{%0,%1,%2,%3},{%4,%5,%6,%7},{%8,%9},{%0,%1,%2,%3};"
        : "+f"(c[0]), "+f"(c[1]), "+f"(c[2]), "+f"(c[3])
        : "r"(a[0]), "r"(a[1]), "r"(a[2]), "r"(a[3]), "r"(b[0]), "r"(b[1]));
}

// ---------------- pack: rearrange weights, combine biases, zero h0/c0 ----------------
__global__ void pack_k(const float* __restrict__ Wf, const float* __restrict__ Wi,
                       const float* __restrict__ Wc, const float* __restrict__ Wo,
                       const float* __restrict__ bf, const float* __restrict__ bi,
                       const float* __restrict__ bc, const float* __restrict__ bo) {
    int idx = blockIdx.x * 256 + threadIdx.x;
    const int TOT = G4 * (INSZ + HH);
    if (idx < TOT) {
        int row = idx / (INSZ + HH);
        int col = idx - row * (INSZ + HH);
        int g = row >> 10, j = row & 1023;
        const float* W = (g == 0) ? Wf : (g == 1) ? Wi : (g == 2) ? Wc : Wo;
        float v = W[(size_t)j * (INSZ + HH) + col];
        if (col < INSZ) d_Wx[(size_t)row * INSZ + col] = v;
        else            d_Wh[(size_t)row * HH + (col - INSZ)] = tf32r(v);
        if (col == 0) {
            const float* b = (g == 0) ? bf : (g == 1) ? bi : (g == 2) ? bc : bo;
            d_bias[row] = b[j];
        }
    }
    if (idx < BB * HH) { d_HS[idx] = 0.f; d_C[idx] = 0.f; }  // h_{-1} = c_{-1} = 0
}

// ---------------- tf32 GEMM: C[outrow(m), n] = sum_k A[m,k]*B[n,k] + bias[n] ----------------
// outrow(m) = (m % Q) * P + m / Q      (batch/time transpose fused into epilogue)
#define GLP 36
template <int KTOT>
__global__ __launch_bounds__(256) void gemm_k(const float* __restrict__ A,
                                              const float* __restrict__ B,
                                              const float* __restrict__ bias,
                                              float* __restrict__ C,
                                              int P, int Q, int N) {
    __shared__ float sA[128 * GLP];
    __shared__ float sB[128 * GLP];
    const int tid = threadIdx.x, lane = tid & 31, wid = tid >> 5;
    const int wm = wid >> 2, wn = wid & 3;
    const long mBase = (long)blockIdx.y * 128;
    const long nBase = (long)blockIdx.x * 128;

    float acc[4][4][4];
#pragma unroll
    for (int a = 0; a < 4; a++)
#pragma unroll
        for (int b = 0; b < 4; b++)
#pragma unroll
            for (int q = 0; q < 4; q++) acc[a][b][q] = 0.f;

    for (int kc = 0; kc < KTOT / 32; kc++) {
#pragma unroll
        for (int i = 0; i < 4; i++) {
            int f = tid + i * 256;
            int row = f >> 3, c4 = (f & 7) * 4;
            float4 va = *(const float4*)(A + (mBase + row) * KTOT + kc * 32 + c4);
            float4 vb = *(const float4*)(B + (nBase + row) * KTOT + kc * 32 + c4);
            float* pa = sA + row * GLP + c4;
            pa[0] = tf32r(va.x); pa[1] = tf32r(va.y); pa[2] = tf32r(va.z); pa[3] = tf32r(va.w);
            float* pb = sB + row * GLP + c4;
            pb[0] = tf32r(vb.x); pb[1] = tf32r(vb.y); pb[2] = tf32r(vb.z); pb[3] = tf32r(vb.w);
        }
        __syncthreads();
#pragma unroll
        for (int ks = 0; ks < 4; ks++) {
            const int kk = ks * 8 + (lane & 3);
            uint32_t af[4][4], bfv[4][2];
#pragma unroll
            for (int mi = 0; mi < 4; mi++) {
                const float* p = sA + (wm * 64 + mi * 16 + (lane >> 2)) * GLP + kk;
                af[mi][0] = __float_as_uint(p[0]);
                af[mi][1] = __float_as_uint(p[8 * GLP]);
                af[mi][2] = __float_as_uint(p[4]);
                af[mi][3] = __float_as_uint(p[8 * GLP + 4]);
            }
#pragma unroll
            for (int ni = 0; ni < 4; ni++) {
                const float* q = sB + (wn * 32 + ni * 8 + (lane >> 2)) * GLP + kk;
                bfv[ni][0] = __float_as_uint(q[0]);
                bfv[ni][1] = __float_as_uint(q[4]);
            }
#pragma unroll
            for (int mi = 0; mi < 4; mi++)
#pragma unroll
                for (int ni = 0; ni < 4; ni++) mma8(acc[mi][ni], af[mi], bfv[ni]);
        }
        __syncthreads();
    }
    // epilogue with (b,t) transpose remap
#pragma unroll
    for (int mi = 0; mi < 4; mi++) {
        int r0 = (int)mBase + wm * 64 + mi * 16 + (lane >> 2);
#pragma unroll
        for (int ni = 0; ni < 4; ni++) {
            int col = (int)nBase + wn * 32 + ni * 8 + 2 * (lane & 3);
            float b0 = bias[col], b1 = bias[col + 1];
#pragma unroll
            for (int p = 0; p < 2; p++) {
                int m = r0 + p * 8;
                long orow = (long)(m % Q) * P + m / Q;
                float2 v = make_float2(acc[mi][ni][2 * p] + b0, acc[mi][ni][2 * p + 1] + b1);
                *(float2*)(C + orow * N + col) = v;
            }
        }
    }
}

// ---------------- one recurrence step (no inter-CTA dependencies) ----------------
// CTA cid owns hidden units cid*8..cid*8+7 (gate rows g*1024 + cid*8 + u, g=0..3).
// Computes Gh = h_{t-1} @ Wh_slice^T  (M=128, N=32, K=1024 in 8 chunks of 128),
// then gates = GX[t] + Gh, cell update, writes h_t.
#define SLP 132
#define STEP_SMEM ((128 * SLP + 32 * SLP + 128 * 33) * 4)

__global__ __launch_bounds__(256, 1) void step_k(int t) {
    extern __shared__ float sm[];
    float* sH = sm;                   // [128][SLP] h chunk
    float* sW = sH + 128 * SLP;       // [32][SLP]  Wh chunk
    float* sG = sW + 32 * SLP;        // [128][33]  gate pre-acts (h part)
    const int tid = threadIdx.x, lane = tid & 31, w = tid >> 5;
    const int cid = blockIdx.x;

    float acc[4][4];
#pragma unroll
    for (int ni = 0; ni < 4; ni++)
#pragma unroll
        for (int q = 0; q < 4; q++) acc[ni][q] = 0.f;

    const float* hbase = d_HS + (size_t)t * BB * HH;

    for (int ch = 0; ch < 8; ch++) {
        // stage h chunk [128 x 128], rounded to tf32 (keep out of L1 - streaming)
        for (int i = tid; i < 4096; i += 256) {
            int b = i >> 5, k4 = (i & 31) * 4;
            float4 v = __ldcg((const float4*)(hbase + (size_t)b * HH + ch * 128 + k4));
            float* p = sH + b * SLP + k4;
            p[0] = tf32r(v.x); p[1] = tf32r(v.y); p[2] = tf32r(v.z); p[3] = tf32r(v.w);
        }
        // stage Wh chunk [32 x 128]: local row n = g*8+u -> global row g*1024 + cid*8 + u
        for (int i = tid; i < 1024; i += 256) {
            int n = i >> 5, k4 = (i & 31) * 4;
            int grow = (n >> 3) * 1024 + cid * 8 + (n & 7);
            float4 v = __ldg((const float4*)(d_Wh + (size_t)grow * HH + ch * 128 + k4));
            float* p = sW + n * SLP + k4;
            p[0] = v.x; p[1] = v.y; p[2] = v.z; p[3] = v.w;
        }
        __syncthreads();
#pragma unroll
        for (int ks = 0; ks < 16; ks++) {
            const int kk = ks * 8 + (lane & 3);
            uint32_t a[4];
            const float* p = sH + (w * 16 + (lane >> 2)) * SLP + kk;
            a[0] = __float_as_uint(p[0]);
            a[1] = __float_as_uint(p[8 * SLP]);
            a[2] = __float_as_uint(p[4]);
            a[3] = __float_as_uint(p[8 * SLP + 4]);
#pragma unroll
            for (int ni = 0; ni < 4; ni++) {
                const float* q = sW + (ni * 8 + (lane >> 2)) * SLP + kk;
                uint32_t bv[2] = { __float_as_uint(q[0]), __float_as_uint(q[4]) };
                mma8(acc[ni], a, bv);
            }
        }
        __syncthreads();
    }

    // scatter fragments to sG: [batch m][local gate row n]
#pragma unroll
    for (int ni = 0; ni < 4; ni++) {
        int m = w * 16 + (lane >> 2);
        int n = ni * 8 + 2 * (lane & 3);
        sG[m * 33 + n]           = acc[ni][0];
        sG[m * 33 + n + 1]       = acc[ni][1];
        sG[(m + 8) * 33 + n]     = acc[ni][2];
        sG[(m + 8) * 33 + n + 1] = acc[ni][3];
    }
    __syncthreads();

    // elementwise: gates = GX + h-part; update c (global), write h_t
    {
        const int eb = tid >> 1, eu0 = (tid & 1) * 4;
        const float* gx = d_GX + ((size_t)t * BB + eb) * G4 + cid * 8 + eu0;
        float4 gf = __ldg((const float4*)(gx));
        float4 gi = __ldg((const float4*)(gx + 1024));
        float4 gc = __ldg((const float4*)(gx + 2048));
        float4 go = __ldg((const float4*)(gx + 3072));
        float* cp = d_C + eb * HH + cid * 8 + eu0;
        float4 cold = *(const float4*)cp;
        float gfv[4] = {gf.x, gf.y, gf.z, gf.w};
        float giv[4] = {gi.x, gi.y, gi.z, gi.w};
        float gcv[4] = {gc.x, gc.y, gc.z, gc.w};
        float gov[4] = {go.x, go.y, go.z, go.w};
        float cv[4]  = {cold.x, cold.y, cold.z, cold.w};
        float hout[4];
#pragma unroll
        for (int u = 0; u < 4; u++) {
            int n = eu0 + u;
            float fg = sigf(gfv[u] + sG[eb * 33 + n]);
            float ig = sigf(giv[u] + sG[eb * 33 + 8 + n]);
            float ct = tanhf_(gcv[u] + sG[eb * 33 + 16 + n]);
            float og = sigf(gov[u] + sG[eb * 33 + 24 + n]);
            float c = fg * cv[u] + ig * ct;
            cv[u] = c;
            hout[u] = og * tanhf_(c);
        }
        *(float4*)cp = make_float4(cv[0], cv[1], cv[2], cv[3]);
        *(float4*)(d_HS + (size_t)(t + 1) * BB * HH + (size_t)eb * HH + cid * 8 + eu0) =
            make_float4(hout[0], hout[1], hout[2], hout[3]);
    }
}

// ---------------- launch ----------------
extern "C" void kernel_launch(void* const* d_in, const int* in_sizes, int n_in,
                              void* d_out, int out_size) {
    const float* x    = (const float*)d_in[0];
    const float* Wf   = (const float*)d_in[1];
    const float* bf   = (const float*)d_in[2];
    const float* Wi   = (const float*)d_in[3];
    const float* bi   = (const float*)d_in[4];
    const float* Wc   = (const float*)d_in[5];
    const float* bc   = (const float*)d_in[6];
    const float* Wo   = (const float*)d_in[7];
    const float* bo   = (const float*)d_in[8];
    const float* Wout = (const float*)d_in[9];
    const float* bout = (const float*)d_in[10];
    float* out = (float*)d_out;

    void *pWx, *pBias, *pGX, *pHS;
    cudaGetSymbolAddress(&pWx, d_Wx);
    cudaGetSymbolAddress(&pBias, d_bias);
    cudaGetSymbolAddress(&pGX, d_GX);
    cudaGetSymbolAddress(&pHS, d_HS);
    cudaFuncSetAttribute(step_k, cudaFuncAttributeMaxDynamicSharedMemorySize, STEP_SMEM);

    // 1) pack weights/biases, zero h0/c0
    pack_k<<<(G4 * (INSZ + HH)) / 256, 256>>>(Wf, Wi, Wc, Wo, bf, bi, bc, bo);
    // 2) GX = x @ Wx^T + bias   (m = b*256+t -> outrow t*128+b)
    gemm_k<INSZ><<<dim3(G4 / 128, (BB * TT) / 128), 256>>>(
        x, (const float*)pWx, (const float*)pBias, (float*)pGX, BB, TT, G4);
    // 3) recurrence: one kernel per time step (no inter-CTA sync anywhere)
    for (int t = 0; t < TT; t++)
        step_k<<<128, 256, STEP_SMEM>>>(t);
    // 4) out = HS @ Wout^T + b_out   (m = t*128+b -> outrow b*256+t)
    gemm_k<HH><<<dim3(ONN / 128, (BB * TT) / 128), 256>>>(
        (const float*)pHS + (size_t)BB * HH, Wout, bout, out, TT, BB, ONN);
}

// round 8
// speedup vs baseline: 1.4229x; 1.4229x over previous
#include <cuda_runtime.h>
#include <cstdint>

#define BB   128
#define TT   256
#define INSZ 512
#define HH   1024
#define G4   4096
#define ONN  512

// ---------------- device scratch (no allocation allowed) ----------------
__device__ float d_Wx[G4 * INSZ];                      // [4096,512]
__device__ float d_Wh[(size_t)G4 * HH];                // [4096,1024] tf32-rounded
__device__ float d_bias[G4];
__device__ float d_GX[(size_t)BB * TT * G4];           // [t*128+b][4096]
__device__ float d_HS[(size_t)(TT + 1) * BB * HH];     // slot t = h_{t-1} (tf32-rounded)
__device__ float d_C[BB * HH];                         // cell state

// ---------------- helpers ----------------
__device__ __forceinline__ float tf32r(float x) {
    uint32_t r; asm("cvt.rna.tf32.f32 %0, %1;" : "=r"(r) : "f"(x));
    return __uint_as_float(r);
}
__device__ __forceinline__ float sigf(float x) { return 1.f / (1.f + __expf(-x)); }
__device__ __forceinline__ float tanhf_(float x) {
    float e = __expf(-2.f * fabsf(x));
    float r = (1.f - e) / (1.f + e);
    return copysignf(r, x);
}
__device__ __forceinline__ void mma8(float* c, const uint32_t* a, const uint32_t* b) {
    asm volatile(
        "mma.sync.aligned.m16n8k8.row.col.f32.tf32.tf32.f32 "
        "{%0,%1,%2,%3},{%4,%5,%6,%7},{%8,%9},{%0,%1,%2,%3};"
        : "+f"(c[0]), "+f"(c[1]), "+f"(c[2]), "+f"(c[3])
        : "r"(a[0]), "r"(a[1]), "r"(a[2]), "r"(a[3]), "r"(b[0]), "r"(b[1]));
}
__device__ __forceinline__ void cpa16(uint32_t dst, const void* src) {
    asm volatile("cp.async.cg.shared.global [%0], [%1], 16;" :: "r"(dst), "l"(src));
}

// ---------------- pack: rearrange weights, combine biases, zero h0/c0 ----------------
__global__ void pack_k(const float* __restrict__ Wf, const float* __restrict__ Wi,
                       const float* __restrict__ Wc, const float* __restrict__ Wo,
                       const float* __restrict__ bf, const float* __restrict__ bi,
                       const float* __restrict__ bc, const float* __restrict__ bo) {
    int idx = blockIdx.x * 256 + threadIdx.x;
    const int TOT = G4 * (INSZ + HH);
    if (idx < TOT) {
        int row = idx / (INSZ + HH);
        int col = idx - row * (INSZ + HH);
        int g = row >> 10, j = row & 1023;
        const float* W = (g == 0) ? Wf : (g == 1) ? Wi : (g == 2) ? Wc : Wo;
        float v = W[(size_t)j * (INSZ + HH) + col];
        if (col < INSZ) d_Wx[(size_t)row * INSZ + col] = v;
        else            d_Wh[(size_t)row * HH + (col - INSZ)] = tf32r(v);
        if (col == 0) {
            const float* b = (g == 0) ? bf : (g == 1) ? bi : (g == 2) ? bc : bo;
            d_bias[row] = b[j];
        }
    }
    if (idx < BB * HH) { d_HS[idx] = 0.f; d_C[idx] = 0.f; }  // h_{-1} = c_{-1} = 0
}

// ---------------- tf32 GEMM: C[outrow(m), n] = sum_k A[m,k]*B[n,k] + bias[n] ----------------
// outrow(m) = (m % Q) * P + m / Q      (batch/time transpose fused into epilogue)
#define GLP 36
template <int KTOT>
__global__ __launch_bounds__(256) void gemm_k(const float* __restrict__ A,
                                              const float* __restrict__ B,
                                              const float* __restrict__ bias,
                                              float* __restrict__ C,
                                              int P, int Q, int N) {
    __shared__ float sA[128 * GLP];
    __shared__ float sB[128 * GLP];
    const int tid = threadIdx.x, lane = tid & 31, wid = tid >> 5;
    const int wm = wid >> 2, wn = wid & 3;
    const long mBase = (long)blockIdx.y * 128;
    const long nBase = (long)blockIdx.x * 128;

    float acc[4][4][4];
#pragma unroll
    for (int a = 0; a < 4; a++)
#pragma unroll
        for (int b = 0; b < 4; b++)
#pragma unroll
            for (int q = 0; q < 4; q++) acc[a][b][q] = 0.f;

    for (int kc = 0; kc < KTOT / 32; kc++) {
#pragma unroll
        for (int i = 0; i < 4; i++) {
            int f = tid + i * 256;
            int row = f >> 3, c4 = (f & 7) * 4;
            float4 va = *(const float4*)(A + (mBase + row) * KTOT + kc * 32 + c4);
            float4 vb = *(const float4*)(B + (nBase + row) * KTOT + kc * 32 + c4);
            float* pa = sA + row * GLP + c4;
            pa[0] = tf32r(va.x); pa[1] = tf32r(va.y); pa[2] = tf32r(va.z); pa[3] = tf32r(va.w);
            float* pb = sB + row * GLP + c4;
            pb[0] = tf32r(vb.x); pb[1] = tf32r(vb.y); pb[2] = tf32r(vb.z); pb[3] = tf32r(vb.w);
        }
        __syncthreads();
#pragma unroll
        for (int ks = 0; ks < 4; ks++) {
            const int kk = ks * 8 + (lane & 3);
            uint32_t af[4][4], bfv[4][2];
#pragma unroll
            for (int mi = 0; mi < 4; mi++) {
                const float* p = sA + (wm * 64 + mi * 16 + (lane >> 2)) * GLP + kk;
                af[mi][0] = __float_as_uint(p[0]);
                af[mi][1] = __float_as_uint(p[8 * GLP]);
                af[mi][2] = __float_as_uint(p[4]);
                af[mi][3] = __float_as_uint(p[8 * GLP + 4]);
            }
#pragma unroll
            for (int ni = 0; ni < 4; ni++) {
                const float* q = sB + (wn * 32 + ni * 8 + (lane >> 2)) * GLP + kk;
                bfv[ni][0] = __float_as_uint(q[0]);
                bfv[ni][1] = __float_as_uint(q[4]);
            }
#pragma unroll
            for (int mi = 0; mi < 4; mi++)
#pragma unroll
                for (int ni = 0; ni < 4; ni++) mma8(acc[mi][ni], af[mi], bfv[ni]);
        }
        __syncthreads();
    }
    // epilogue with (b,t) transpose remap
#pragma unroll
    for (int mi = 0; mi < 4; mi++) {
        int r0 = (int)mBase + wm * 64 + mi * 16 + (lane >> 2);
#pragma unroll
        for (int ni = 0; ni < 4; ni++) {
            int col = (int)nBase + wn * 32 + ni * 8 + 2 * (lane & 3);
            float b0 = bias[col], b1 = bias[col + 1];
#pragma unroll
            for (int p = 0; p < 2; p++) {
                int m = r0 + p * 8;
                long orow = (long)(m % Q) * P + m / Q;
                float2 v = make_float2(acc[mi][ni][2 * p] + b0, acc[mi][ni][2 * p + 1] + b1);
                *(float2*)(C + orow * N + col) = v;
            }
        }
    }
}

// ---------------- one recurrence step: cp.async double-buffered ----------------
// CTA cid owns hidden units cid*8..cid*8+7 (gate rows g*1024 + cid*8 + u, g=0..3).
// Gh = h_{t-1} @ Wh_slice^T  (M=128, N=32, K=1024 in 8 chunks of 128, 2-stage pipe).
#define SLP 132                       // floats; 132*4=528B = 33*16 -> 16B aligned rows
#define HSTG (128 * SLP)
#define WSTG (32 * SLP)
#define STEP_SMEM ((2 * HSTG + 2 * WSTG + 128 * 33) * 4)

__global__ __launch_bounds__(256, 1) void step_k(int t) {
    extern __shared__ float sm[];
    float* sH = sm;                    // [2][128][SLP]
    float* sW = sH + 2 * HSTG;         // [2][32][SLP]
    float* sG = sW + 2 * WSTG;         // [128][33]
    const int tid = threadIdx.x, lane = tid & 31, w = tid >> 5;
    const int cid = blockIdx.x;
    const float* hbase = d_HS + (size_t)t * BB * HH;

    uint32_t shBase = (uint32_t)__cvta_generic_to_shared(sH);
    uint32_t swBase = (uint32_t)__cvta_generic_to_shared(sW);

    auto load_chunk = [&](int ch) {
        int s = ch & 1;
        // h chunk: 128 rows x 32 x 16B
#pragma unroll
        for (int i = 0; i < 16; i++) {
            int f = tid + i * 256;
            int row = f >> 5, seg = f & 31;
            cpa16(shBase + (s * HSTG + row * SLP + seg * 4) * 4,
                  hbase + (size_t)row * HH + ch * 128 + seg * 4);
        }
        // Wh chunk: 32 rows x 32 x 16B  (local row n = g*8+u -> global g*1024+cid*8+u)
#pragma unroll
        for (int i = 0; i < 4; i++) {
            int f = tid + i * 256;
            int n = f >> 5, seg = f & 31;
            int grow = (n >> 3) * 1024 + cid * 8 + (n & 7);
            cpa16(swBase + (s * WSTG + n * SLP + seg * 4) * 4,
                  d_Wh + (size_t)grow * HH + ch * 128 + seg * 4);
        }
        asm volatile("cp.async.commit_group;");
    };

    float acc[4][4];
#pragma unroll
    for (int ni = 0; ni < 4; ni++)
#pragma unroll
        for (int q = 0; q < 4; q++) acc[ni][q] = 0.f;

    load_chunk(0);
    for (int ch = 0; ch < 8; ch++) {
        if (ch + 1 < 8) {
            load_chunk(ch + 1);
            asm volatile("cp.async.wait_group 1;");
        } else {
            asm volatile("cp.async.wait_group 0;");
        }
        __syncthreads();
        const float* Hs = sH + (ch & 1) * HSTG;
        const float* Ws = sW + (ch & 1) * WSTG;
#pragma unroll
        for (int ks = 0; ks < 16; ks++) {
            const int kk = ks * 8 + (lane & 3);
            uint32_t a[4];
            const float* p = Hs + (w * 16 + (lane >> 2)) * SLP + kk;
            a[0] = __float_as_uint(p[0]);
            a[1] = __float_as_uint(p[8 * SLP]);
            a[2] = __float_as_uint(p[4]);
            a[3] = __float_as_uint(p[8 * SLP + 4]);
#pragma unroll
            for (int ni = 0; ni < 4; ni++) {
                const float* q = Ws + (ni * 8 + (lane >> 2)) * SLP + kk;
                uint32_t bv[2] = { __float_as_uint(q[0]), __float_as_uint(q[4]) };
                mma8(acc[ni], a, bv);
            }
        }
        __syncthreads();
    }

    // scatter fragments to sG: [batch m][local gate row n]
#pragma unroll
    for (int ni = 0; ni < 4; ni++) {
        int m = w * 16 + (lane >> 2);
        int n = ni * 8 + 2 * (lane & 3);
        sG[m * 33 + n]           = acc[ni][0];
        sG[m * 33 + n + 1]       = acc[ni][1];
        sG[(m + 8) * 33 + n]     = acc[ni][2];
        sG[(m + 8) * 33 + n + 1] = acc[ni][3];
    }
    __syncthreads();

    // elementwise: gates = GX + h-part; update c (global), write h_t (tf32-rounded)
    {
        const int eb = tid >> 1, eu0 = (tid & 1) * 4;
        const float* gx = d_GX + ((size_t)t * BB + eb) * G4 + cid * 8 + eu0;
        float4 gf = __ldcs((const float4*)(gx));          // streaming: evict-first
        float4 gi = __ldcs((const float4*)(gx + 1024));
        float4 gc = __ldcs((const float4*)(gx + 2048));
        float4 go = __ldcs((const float4*)(gx + 3072));
        float* cp = d_C + eb * HH + cid * 8 + eu0;
        float4 cold = *(const float4*)cp;
        float gfv[4] = {gf.x, gf.y, gf.z, gf.w};
        float giv[4] = {gi.x, gi.y, gi.z, gi.w};
        float gcv[4] = {gc.x, gc.y, gc.z, gc.w};
        float gov[4] = {go.x, go.y, go.z, go.w};
        float cv[4]  = {cold.x, cold.y, cold.z, cold.w};
        float hout[4];
#pragma unroll
        for (int u = 0; u < 4; u++) {
            int n = eu0 + u;
            float fg = sigf(gfv[u] + sG[eb * 33 + n]);
            float ig = sigf(giv[u] + sG[eb * 33 + 8 + n]);
            float ct = tanhf_(gcv[u] + sG[eb * 33 + 16 + n]);
            float og = sigf(gov[u] + sG[eb * 33 + 24 + n]);
            float c = fg * cv[u] + ig * ct;
            cv[u] = c;
            hout[u] = tf32r(og * tanhf_(c));   // pre-round h so next step raw-copies
        }
        *(float4*)cp = make_float4(cv[0], cv[1], cv[2], cv[3]);
        *(float4*)(d_HS + (size_t)(t + 1) * BB * HH + (size_t)eb * HH + cid * 8 + eu0) =
            make_float4(hout[0], hout[1], hout[2], hout[3]);
    }
}

// ---------------- launch ----------------
extern "C" void kernel_launch(void* const* d_in, const int* in_sizes, int n_in,
                              void* d_out, int out_size) {
    const float* x    = (const float*)d_in[0];
    const float* Wf   = (const float*)d_in[1];
    const float* bf   = (const float*)d_in[2];
    const float* Wi   = (const float*)d_in[3];
    const float* bi   = (const float*)d_in[4];
    const float* Wc   = (const float*)d_in[5];
    const float* bc   = (const float*)d_in[6];
    const float* Wo   = (const float*)d_in[7];
    const float* bo   = (const float*)d_in[8];
    const float* Wout = (const float*)d_in[9];
    const float* bout = (const float*)d_in[10];
    float* out = (float*)d_out;

    void *pWx, *pBias, *pGX, *pHS;
    cudaGetSymbolAddress(&pWx, d_Wx);
    cudaGetSymbolAddress(&pBias, d_bias);
    cudaGetSymbolAddress(&pGX, d_GX);
    cudaGetSymbolAddress(&pHS, d_HS);
    cudaFuncSetAttribute(step_k, cudaFuncAttributeMaxDynamicSharedMemorySize, STEP_SMEM);

    // 1) pack weights/biases, zero h0/c0
    pack_k<<<(G4 * (INSZ + HH)) / 256, 256>>>(Wf, Wi, Wc, Wo, bf, bi, bc, bo);
    // 2) GX = x @ Wx^T + bias   (m = b*256+t -> outrow t*128+b)
    gemm_k<INSZ><<<dim3(G4 / 128, (BB * TT) / 128), 256>>>(
        x, (const float*)pWx, (const float*)pBias, (float*)pGX, BB, TT, G4);
    // 3) recurrence: one kernel per time step (no inter-CTA sync anywhere)
    for (int t = 0; t < TT; t++)
        step_k<<<128, 256, STEP_SMEM>>>(t);
    // 4) out = HS @ Wout^T + b_out   (m = t*128+b -> outrow b*256+t)
    gemm_k<HH><<<dim3(ONN / 128, (BB * TT) / 128), 256>>>(
        (const float*)pHS + (size_t)BB * HH, Wout, bout, out, TT, BB, ONN);
}

// round 10
// speedup vs baseline: 1.4859x; 1.0443x over previous
#include <cuda_runtime.h>
#include <cstdint>

#define BB   128
#define TT   256
#define INSZ 512
#define HH   1024
#define G4   4096
#define ONN  512

// k-permutation within 8-groups: (k, k+4) become adjacent -> LDS.64 fragment loads
#define PP(j)  (((j) & ~7) | (((j) & 3) << 1) | (((j) >> 2) & 1))

// ---------------- device scratch (no allocation allowed) ----------------
__device__ float d_Wx[G4 * INSZ];                      // [4096,512]
__device__ float d_Wh[(size_t)G4 * HH];                // [4096,1024] tf32 + k-perm
__device__ float d_WoutP[ONN * HH];                    // Wout with k-perm
__device__ float d_bias[G4];
__device__ float d_GX[(size_t)BB * TT * G4];           // [t*128+b][4096]
__device__ float d_HS[(size_t)(TT + 1) * BB * HH];     // slot t = h_{t-1}, tf32 + k-perm
__device__ float d_C[BB * HH];                         // cell state

// ---------------- helpers ----------------
__device__ __forceinline__ float tf32r(float x) {
    uint32_t r; asm("cvt.rna.tf32.f32 %0, %1;" : "=r"(r) : "f"(x));
    return __uint_as_float(r);
}
__device__ __forceinline__ float sigf(float x) { return 1.f / (1.f + __expf(-x)); }
__device__ __forceinline__ float tanhf_(float x) {
    float e = __expf(-2.f * fabsf(x));
    float r = (1.f - e) / (1.f + e);
    return copysignf(r, x);
}
__device__ __forceinline__ void mma8(float* c, const uint32_t* a, const uint32_t* b) {
    asm volatile(
        "mma.sync.aligned.m16n8k8.row.col.f32.tf32.tf32.f32 "
        "{%0,%1,%2,%3},{%4,%5,%6,%7},{%8,%9},{%0,%1,%2,%3};"
        : "+f"(c[0]), "+f"(c[1]), "+f"(c[2]), "+f"(c[3])
        : "r"(a[0]), "r"(a[1]), "r"(a[2]), "r"(a[3]), "r"(b[0]), "r"(b[1]));
}
__device__ __forceinline__ void cpa16(uint32_t dst, const void* src) {
    asm volatile("cp.async.cg.shared.global [%0], [%1], 16;" :: "r"(dst), "l"(src));
}

// ---------------- pack: weights (tf32 + perm), biases, h0/c0 ----------------
__global__ void pack_k(const float* __restrict__ Wf, const float* __restrict__ Wi,
                       const float* __restrict__ Wc, const float* __restrict__ Wo,
                       const float* __restrict__ bf, const float* __restrict__ bi,
                       const float* __restrict__ bc, const float* __restrict__ bo,
                       const float* __restrict__ Wout) {
    int idx = blockIdx.x * 256 + threadIdx.x;
    const int TOT = G4 * (INSZ + HH);
    if (idx < TOT) {
        int row = idx / (INSZ + HH);
        int col = idx - row * (INSZ + HH);
        int g = row >> 10, j = row & 1023;
        const float* W = (g == 0) ? Wf : (g == 1) ? Wi : (g == 2) ? Wc : Wo;
        float v = W[(size_t)j * (INSZ + HH) + col];
        if (col < INSZ) d_Wx[(size_t)row * INSZ + col] = v;
        else {
            int kc = col - INSZ;
            d_Wh[(size_t)row * HH + PP(kc)] = tf32r(v);
        }
        if (col == 0) {
            const float* b = (g == 0) ? bf : (g == 1) ? bi : (g == 2) ? bc : bo;
            d_bias[row] = b[j];
        }
    }
    if (idx < ONN * HH) {
        int o = idx / HH, k = idx - o * HH;
        d_WoutP[o * HH + PP(k)] = Wout[idx];
    }
    if (idx < BB * HH) { d_HS[idx] = 0.f; d_C[idx] = 0.f; }   // h_{-1}=c_{-1}=0
}

// ---------------- tf32 GEMM: C[outrow(m), n] = sum_k A[m,k]*B[n,k] + bias[n] ----------------
// outrow(m) = (m % Q) * P + m / Q   (batch/time transpose fused into epilogue)
#define GLP 36
template <int KTOT>
__global__ __launch_bounds__(256) void gemm_k(const float* __restrict__ A,
                                              const float* __restrict__ B,
                                              const float* __restrict__ bias,
                                              float* __restrict__ C,
                                              int P, int Q, int N) {
    __shared__ float sA[128 * GLP];
    __shared__ float sB[128 * GLP];
    const int tid = threadIdx.x, lane = tid & 31, wid = tid >> 5;
    const int wm = wid >> 2, wn = wid & 3;
    const long mBase = (long)blockIdx.y * 128;
    const long nBase = (long)blockIdx.x * 128;

    float acc[4][4][4];
#pragma unroll
    for (int a = 0; a < 4; a++)
#pragma unroll
        for (int b = 0; b < 4; b++)
#pragma unroll
            for (int q = 0; q < 4; q++) acc[a][b][q] = 0.f;

    for (int kc = 0; kc < KTOT / 32; kc++) {
#pragma unroll
        for (int i = 0; i < 4; i++) {
            int f = tid + i * 256;
            int row = f >> 3, c4 = (f & 7) * 4;
            float4 va = *(const float4*)(A + (mBase + row) * KTOT + kc * 32 + c4);
            float4 vb = *(const float4*)(B + (nBase + row) * KTOT + kc * 32 + c4);
            float* pa = sA + row * GLP + c4;
            pa[0] = tf32r(va.x); pa[1] = tf32r(va.y); pa[2] = tf32r(va.z); pa[3] = tf32r(va.w);
            float* pb = sB + row * GLP + c4;
            pb[0] = tf32r(vb.x); pb[1] = tf32r(vb.y); pb[2] = tf32r(vb.z); pb[3] = tf32r(vb.w);
        }
        __syncthreads();
#pragma unroll
        for (int ks = 0; ks < 4; ks++) {
            const int kk = ks * 8 + (lane & 3);
            uint32_t af[4][4], bfv[4][2];
#pragma unroll
            for (int mi = 0; mi < 4; mi++) {
                const float* p = sA + (wm * 64 + mi * 16 + (lane >> 2)) * GLP + kk;
                af[mi][0] = __float_as_uint(p[0]);
                af[mi][1] = __float_as_uint(p[8 * GLP]);
                af[mi][2] = __float_as_uint(p[4]);
                af[mi][3] = __float_as_uint(p[8 * GLP + 4]);
            }
#pragma unroll
            for (int ni = 0; ni < 4; ni++) {
                const float* q = sB + (wn * 32 + ni * 8 + (lane >> 2)) * GLP + kk;
                bfv[ni][0] = __float_as_uint(q[0]);
                bfv[ni][1] = __float_as_uint(q[4]);
            }
#pragma unroll
            for (int mi = 0; mi < 4; mi++)
#pragma unroll
                for (int ni = 0; ni < 4; ni++) mma8(acc[mi][ni], af[mi], bfv[ni]);
        }
        __syncthreads();
    }
#pragma unroll
    for (int mi = 0; mi < 4; mi++) {
        int r0 = (int)mBase + wm * 64 + mi * 16 + (lane >> 2);
#pragma unroll
        for (int ni = 0; ni < 4; ni++) {
            int col = (int)nBase + wn * 32 + ni * 8 + 2 * (lane & 3);
            float b0 = bias[col], b1 = bias[col + 1];
#pragma unroll
            for (int p = 0; p < 2; p++) {
                int m = r0 + p * 8;
                long orow = (long)(m % Q) * P + m / Q;
                float2 v = make_float2(acc[mi][ni][2 * p] + b0, acc[mi][ni][2 * p + 1] + b1);
                *(float2*)(C + orow * N + col) = v;
            }
        }
    }
}

// ---------------- one recurrence step: 512 threads, LDS.64 frags, 2-stage pipe -------------
// CTA cid owns hidden units cid*8..cid*8+7 (gate rows g*1024+cid*8+u).
// 16 warps: warp w -> m-rows (w&7)*16..+16, n-half (w>>3)*16..+16.
#define SRS 136                      // smem row stride (floats); 136 % 32 == 8 banks
#define HBUF (128 * SRS)
#define WBUF (32 * SRS)
#define STEP_SMEM ((2 * HBUF + 2 * WBUF + 128 * 33) * 4)   // 190,976 B

__global__ __launch_bounds__(512, 1) void step_k(int t) {
    extern __shared__ float sm[];
    float* sH = sm;                    // [2][128][SRS]
    float* sW = sm + 2 * HBUF;         // [2][32][SRS]
    float* sG = sW + 2 * WBUF;         // [128][33]
    const int tid = threadIdx.x, lane = tid & 31, w = tid >> 5;
    const int cid = blockIdx.x;
    const int wm = (w & 7) * 16, wn = (w >> 3) * 16;
    const float* hbase = d_HS + (size_t)t * BB * HH;

    uint32_t shB = (uint32_t)__cvta_generic_to_shared(sH);
    uint32_t swB = (uint32_t)__cvta_generic_to_shared(sW);

    auto loadC = [&](int ch) {
        int s = ch & 1;
        // h chunk: 128 rows x 32 x 16B = 4096 segs / 512 thr
#pragma unroll
        for (int i = 0; i < 8; i++) {
            int f = tid + i * 512;
            int row = f >> 5, seg = f & 31;
            cpa16(shB + (s * HBUF + row * SRS + seg * 4) * 4,
                  hbase + (size_t)row * HH + ch * 128 + seg * 4);
        }
        // Wh chunk: 32 rows x 32 x 16B = 1024 segs / 512 thr
#pragma unroll
        for (int i = 0; i < 2; i++) {
            int f = tid + i * 512;
            int n = f >> 5, seg = f & 31;
            int grow = (n >> 3) * 1024 + cid * 8 + (n & 7);
            cpa16(swB + (s * WBUF + n * SRS + seg * 4) * 4,
                  d_Wh + (size_t)grow * HH + ch * 128 + seg * 4);
        }
        asm volatile("cp.async.commit_group;");
    };

    float acc[2][4];
#pragma unroll
    for (int ni = 0; ni < 2; ni++)
#pragma unroll
        for (int q = 0; q < 4; q++) acc[ni][q] = 0.f;

    loadC(0);
    for (int ch = 0; ch < 8; ch++) {
        if (ch + 1 < 8) {
            loadC(ch + 1);
            asm volatile("cp.async.wait_group 1;");
        } else {
            asm volatile("cp.async.wait_group 0;");
        }
        __syncthreads();
        const float* Hs = sH + (ch & 1) * HBUF;
        const float* Ws = sW + (ch & 1) * WBUF;
#pragma unroll
        for (int ks = 0; ks < 16; ks++) {
            const int kk2 = ks * 8 + (lane & 3) * 2;       // perm: (k, k+4) adjacent
            float2 a01 = *(const float2*)(Hs + (wm + (lane >> 2)) * SRS + kk2);
            float2 a23 = *(const float2*)(Hs + (wm + 8 + (lane >> 2)) * SRS + kk2);
            uint32_t a[4] = { __float_as_uint(a01.x), __float_as_uint(a23.x),
                              __float_as_uint(a01.y), __float_as_uint(a23.y) };
#pragma unroll
            for (int ni = 0; ni < 2; ni++) {
                float2 bb = *(const float2*)(Ws + (wn + ni * 8 + (lane >> 2)) * SRS + kk2);
                uint32_t bv[2] = { __float_as_uint(bb.x), __float_as_uint(bb.y) };
                mma8(acc[ni], a, bv);
            }
        }
        __syncthreads();   // buffer (ch&1) reusable at ch+2
    }

    // scatter fragments to sG: [batch m][local gate row n]
#pragma unroll
    for (int ni = 0; ni < 2; ni++) {
        int m = wm + (lane >> 2);
        int n = wn + ni * 8 + 2 * (lane & 3);
        sG[m * 33 + n]           = acc[ni][0];
        sG[m * 33 + n + 1]       = acc[ni][1];
        sG[(m + 8) * 33 + n]     = acc[ni][2];
        sG[(m + 8) * 33 + n + 1] = acc[ni][3];
    }
    __syncthreads();

    // elementwise (512 thr): each thread handles batch eb, 2 hidden units
    {
        const int eb = tid >> 2, eu0 = (tid & 3) * 2;
        const float* gx = d_GX + ((size_t)t * BB + eb) * G4 + cid * 8 + eu0;
        float2 gf = __ldcs((const float2*)(gx));
        float2 gi = __ldcs((const float2*)(gx + 1024));
        float2 gc = __ldcs((const float2*)(gx + 2048));
        float2 go = __ldcs((const float2*)(gx + 3072));
        float* cp = d_C + eb * HH + cid * 8 + eu0;
        float2 cold = *(const float2*)cp;
        float gfv[2] = {gf.x, gf.y}, giv[2] = {gi.x, gi.y};
        float gcv[2] = {gc.x, gc.y}, gov[2] = {go.x, go.y};
        float cv[2] = {cold.x, cold.y};
        float* hdst = d_HS + (size_t)(t + 1) * BB * HH + (size_t)eb * HH + cid * 8;
#pragma unroll
        for (int u = 0; u < 2; u++) {
            int n = eu0 + u;
            float fg = sigf(gfv[u] + sG[eb * 33 + n]);
            float ig = sigf(giv[u] + sG[eb * 33 + 8 + n]);
            float ct = tanhf_(gcv[u] + sG[eb * 33 + 16 + n]);
            float og = sigf(gov[u] + sG[eb * 33 + 24 + n]);
            float c = fg * cv[u] + ig * ct;
            cv[u] = c;
            int pos = ((n & 3) << 1) | ((n >> 2) & 1);     // PP within 8-group
            hdst[pos] = tf32r(og * tanhf_(c));
        }
        *(float2*)cp = make_float2(cv[0], cv[1]);
    }
}

// ---------------- launch ----------------
extern "C" void kernel_launch(void* const* d_in, const int* in_sizes, int n_in,
                              void* d_out, int out_size) {
    const float* x    = (const float*)d_in[0];
    const float* Wf   = (const float*)d_in[1];
    const float* bf   = (const float*)d_in[2];
    const float* Wi   = (const float*)d_in[3];
    const float* bi   = (const float*)d_in[4];
    const float* Wc   = (const float*)d_in[5];
    const float* bc   = (const float*)d_in[6];
    const float* Wo   = (const float*)d_in[7];
    const float* bo   = (const float*)d_in[8];
    const float* Wout = (const float*)d_in[9];
    const float* bout = (const float*)d_in[10];
    float* out = (float*)d_out;

    void *pWx, *pBias, *pGX, *pHS, *pWoutP;
    cudaGetSymbolAddress(&pWx, d_Wx);
    cudaGetSymbolAddress(&pBias, d_bias);
    cudaGetSymbolAddress(&pGX, d_GX);
    cudaGetSymbolAddress(&pHS, d_HS);
    cudaGetSymbolAddress(&pWoutP, d_WoutP);
    cudaFuncSetAttribute(step_k, cudaFuncAttributeMaxDynamicSharedMemorySize, STEP_SMEM);

    // 1) pack weights/biases (tf32 + k-perm), zero h0/c0
    pack_k<<<(G4 * (INSZ + HH)) / 256, 256>>>(Wf, Wi, Wc, Wo, bf, bi, bc, bo, Wout);
    // 2) GX = x @ Wx^T + bias   (m = b*256+t -> outrow t*128+b)
    gemm_k<INSZ><<<dim3(G4 / 128, (BB * TT) / 128), 256>>>(
        x, (const float*)pWx, (const float*)pBias, (float*)pGX, BB, TT, G4);
    // 3) recurrence: one kernel per time step (no inter-CTA sync anywhere)
    for (int t = 0; t < TT; t++)
        step_k<<<128, 512, STEP_SMEM>>>(t);
    // 4) out = HS @ WoutP^T + b_out  (HS and WoutP share the k-perm -> dot unchanged)
    gemm_k<HH><<<dim3(ONN / 128, (BB * TT) / 128), 256>>>(
        (const float*)pHS + (size_t)BB * HH, (const float*)pWoutP, bout, out, TT, BB, ONN);
}